// round 4
// baseline (speedup 1.0000x reference)
#include <cuda_runtime.h>

#define L_DIM 8192
#define B_DIM 4096
#define B4 1024            // float4 lanes per row
#define RANK 8
#define LANES 8            // float4 lanes per b-stripe (32 floats)
#define SLICES 32          // m-parallel slices per CTA
#define NTHREADS 256
#define MB 512             // m per V-staging block
#define LB 256             // l per U-staging block

typedef unsigned long long u64;

__device__ __forceinline__ void fma2(u64& d, u64 a, u64 b) {
    asm("fma.rn.f32x2 %0, %1, %2, %0;" : "+l"(d) : "l"(a), "l"(b));
}
__device__ __forceinline__ u64 dup2(float v) {
    u64 r;
    asm("mov.b64 %0, {%1, %1};" : "=l"(r) : "f"(v));
    return r;
}
__device__ __forceinline__ u64 pack2(float x, float y) {
    u64 r;
    asm("mov.b64 %0, {%1, %2};" : "=l"(r) : "f"(x), "f"(y));
    return r;
}
__device__ __forceinline__ float2 unpk2(u64 a) {
    float2 f;
    asm("mov.b64 {%0, %1}, %2;" : "=f"(f.x), "=f"(f.y) : "l"(a));
    return f;
}

__global__ __launch_bounds__(NTHREADS) void fused_kernel(
    const float* __restrict__ inp, const float* __restrict__ U,
    const float* __restrict__ V, float* __restrict__ out)
{
    // 32 KB scratch, reused: Vs_dup[8][512] u64 -> red[32][8][8] float4 -> Us_dup[8][256] u64
    __shared__ __align__(16) char s_buf[RANK * MB * sizeof(u64)];
    __shared__ __align__(16) float4 s_T[RANK][LANES];

    const int t = threadIdx.x;
    const int lane = t & 7;           // b4 lane within stripe
    const int slice = t >> 3;         // m/l slice 0..31
    const int b4g = blockIdx.x * LANES + lane;

    const double2* in2 = (const double2*)inp;

    // ---------------- Phase 1: T = V @ x for this b-stripe ----------------
    u64* Vs = (u64*)s_buf;            // [RANK][MB], duplicated pairs

    u64 acc[RANK][2];
    #pragma unroll
    for (int r = 0; r < RANK; r++) { acc[r][0] = 0ull; acc[r][1] = 0ull; }

    for (int mb = 0; mb < L_DIM; mb += MB) {
        for (int i = t; i < RANK * MB; i += NTHREADS) {
            int r = i >> 9;           // /MB
            int mi = i & (MB - 1);
            Vs[r * MB + mi] = dup2(V[r * L_DIM + mb + mi]);
        }
        __syncthreads();

        #pragma unroll 8
        for (int k = 0; k < MB / SLICES; k++) {
            int ml = k * SLICES + slice;
            double2 x = __ldcs(&in2[(size_t)(mb + ml) * B4 + b4g]);
            u64 xlo = (u64)__double_as_longlong(x.x);
            u64 xhi = (u64)__double_as_longlong(x.y);
            #pragma unroll
            for (int r = 0; r < RANK; r++) {
                u64 v2 = Vs[r * MB + ml];
                fma2(acc[r][0], v2, xlo);
                fma2(acc[r][1], v2, xhi);
            }
        }
        __syncthreads();              // guard Vs reuse (and later s_buf reuse)
    }

    // reduce 32 slices -> s_T[r][lane]
    float4* red = (float4*)s_buf;     // [SLICES][RANK][LANES]
    #pragma unroll
    for (int r = 0; r < RANK; r++) {
        float2 lo = unpk2(acc[r][0]);
        float2 hi = unpk2(acc[r][1]);
        float4 a = make_float4(lo.x, lo.y, hi.x, hi.y);
        red[(slice * RANK + r) * LANES + lane] = a;
    }
    __syncthreads();
    if (t < RANK * LANES) {
        int r = t >> 3, ln = t & 7;
        float4 s = red[(size_t)(0 * RANK + r) * LANES + ln];
        #pragma unroll
        for (int sl = 1; sl < SLICES; sl++) {
            float4 x = red[(sl * RANK + r) * LANES + ln];
            s.x += x.x; s.y += x.y; s.z += x.z; s.w += x.w;
        }
        s_T[r][ln] = s;
    }
    __syncthreads();

    // each thread keeps T for its lane in registers (packed pairs)
    u64 tld[RANK][2];
    #pragma unroll
    for (int r = 0; r < RANK; r++) {
        float4 v = s_T[r][lane];
        tld[r][0] = pack2(v.x, v.y);
        tld[r][1] = pack2(v.z, v.w);
    }

    // ---------------- Phase 2: out[l, stripe] = U^T @ T ----------------
    u64* Us = (u64*)s_buf;            // [RANK][LB], duplicated pairs
    float4* out4 = (float4*)out;

    for (int lb = 0; lb < L_DIM; lb += LB) {
        __syncthreads();              // guard s_buf reuse
        for (int i = t; i < RANK * LB; i += NTHREADS) {
            int r = i >> 8;           // /LB
            int li = i & (LB - 1);
            Us[r * LB + li] = dup2(U[r * L_DIM + lb + li]);
        }
        __syncthreads();

        #pragma unroll
        for (int j = 0; j < LB / SLICES; j++) {
            int ll = j * SLICES + slice;
            u64 a0 = 0ull, a1 = 0ull;
            #pragma unroll
            for (int r = 0; r < RANK; r++) {
                u64 u2 = Us[r * LB + ll];
                fma2(a0, u2, tld[r][0]);
                fma2(a1, u2, tld[r][1]);
            }
            float2 lo = unpk2(a0);
            float2 hi = unpk2(a1);
            float4 o = make_float4(lo.x, lo.y, hi.x, hi.y);
            __stcs(&out4[(size_t)(lb + ll) * B4 + b4g], o);
        }
    }
}

extern "C" void kernel_launch(void* const* d_in, const int* in_sizes, int n_in,
                              void* d_out, int out_size) {
    const float* inp = (const float*)d_in[0];  // [L, B]
    const float* U   = (const float*)d_in[1];  // [RANK, L]
    const float* V   = (const float*)d_in[2];  // [RANK, L]
    float* out = (float*)d_out;                // [L, B]

    fused_kernel<<<B4 / LANES, NTHREADS>>>(inp, U, V, out);  // 128 CTAs
}

// round 5
// speedup vs baseline: 1.8892x; 1.8892x over previous
#include <cuda_runtime.h>

#define L_DIM 8192
#define B_DIM 4096
#define RANK 8
#define M_SPLITS 128
#define M_CHUNK (L_DIM / M_SPLITS)   // 64
#define B4 (B_DIM / 4)               // 1024 float4 lanes
#define L_TILE 32

typedef unsigned long long u64;

__device__ __forceinline__ void fma2(u64& d, u64 a, u64 b) {
    asm("fma.rn.f32x2 %0, %1, %2, %0;" : "+l"(d) : "l"(a), "l"(b));
}
__device__ __forceinline__ u64 dup2(float v) {
    u64 r;
    asm("mov.b64 %0, {%1, %1};" : "=l"(r) : "f"(v));
    return r;
}
__device__ __forceinline__ u64 pack2(float x, float y) {
    u64 r;
    asm("mov.b64 %0, {%1, %2};" : "=l"(r) : "f"(x), "f"(y));
    return r;
}
__device__ __forceinline__ float2 unpk2(u64 a) {
    float2 f;
    asm("mov.b64 {%0, %1}, %2;" : "=f"(f.x), "=f"(f.y) : "l"(a));
    return f;
}

// per-split partials: [M_SPLITS][RANK][B_DIM] = 16 MB (L2-resident)
__device__ float g_part[M_SPLITS * RANK * B_DIM];
// reduced T = V @ inputs -> [RANK, B]
__device__ float g_T[RANK * B_DIM];

// stage 1: part[s, r, b] = sum_{m in chunk s} V[r, m] * inputs[m, b]
// grid: (B4/256 = 4, M_SPLITS = 128), block: 256
__global__ __launch_bounds__(256, 4) void vx_part_kernel(
    const float* __restrict__ inp, const float* __restrict__ V) {
    __shared__ u64 Vs[RANK][M_CHUNK];   // duplicated pairs, 4 KB

    const int s = blockIdx.y;
    const int m0 = s * M_CHUNK;
    for (int i = threadIdx.x; i < RANK * M_CHUNK; i += blockDim.x) {
        int r = i >> 6;               // / M_CHUNK
        int mi = i & (M_CHUNK - 1);
        Vs[r][mi] = dup2(V[r * L_DIM + m0 + mi]);
    }
    __syncthreads();

    const int b4 = blockIdx.x * blockDim.x + threadIdx.x;  // 0..1023
    const double2* in2 = (const double2*)inp;   // float4 as 2x u64 halves

    u64 acc[RANK][2];
    #pragma unroll
    for (int r = 0; r < RANK; r++) { acc[r][0] = 0ull; acc[r][1] = 0ull; }

    #pragma unroll 2
    for (int mi = 0; mi < M_CHUNK; mi++) {
        double2 x = __ldcs(&in2[(size_t)(m0 + mi) * B4 + b4]);
        u64 xlo = (u64)__double_as_longlong(x.x);
        u64 xhi = (u64)__double_as_longlong(x.y);
        #pragma unroll
        for (int r = 0; r < RANK; r++) {
            u64 v2 = Vs[r][mi];
            fma2(acc[r][0], v2, xlo);
            fma2(acc[r][1], v2, xhi);
        }
    }

    float4* p4 = (float4*)g_part;
    #pragma unroll
    for (int r = 0; r < RANK; r++) {
        float2 lo = unpk2(acc[r][0]);
        float2 hi = unpk2(acc[r][1]);
        p4[((size_t)s * RANK + r) * B4 + b4] = make_float4(lo.x, lo.y, hi.x, hi.y);
    }
}

// stage 2: T[r, b] = sum_s part[s, r, b]   (reads from L2)
// grid: RANK*B4/256 = 32 blocks, block: 256 (one float4 per thread)
__global__ __launch_bounds__(256) void reduce_kernel() {
    const int idx = blockIdx.x * blockDim.x + threadIdx.x;  // 0..8191
    const float4* p4 = (const float4*)g_part;

    float4 acc = make_float4(0.f, 0.f, 0.f, 0.f);
    #pragma unroll 16
    for (int s = 0; s < M_SPLITS; s++) {
        float4 x = p4[(size_t)s * RANK * B4 + idx];
        acc.x += x.x; acc.y += x.y; acc.z += x.z; acc.w += x.w;
    }
    ((float4*)g_T)[idx] = acc;
}

// stage 3: out[l, b] = sum_r U[r, l] * T[r, b]
// grid: (B4/256 = 4, L_DIM / L_TILE = 256), block: 256
__global__ __launch_bounds__(256, 4) void out_kernel(
    const float* __restrict__ U, float* __restrict__ out) {
    __shared__ u64 Us[RANK][L_TILE];    // duplicated pairs, 2 KB

    const int l0 = blockIdx.y * L_TILE;
    for (int i = threadIdx.x; i < RANK * L_TILE; i += blockDim.x) {
        int r = i >> 5;               // / L_TILE
        int li = i & (L_TILE - 1);
        Us[r][li] = dup2(U[r * L_DIM + l0 + li]);
    }
    __syncthreads();

    const int b4 = blockIdx.x * blockDim.x + threadIdx.x;  // 0..1023
    const float4* T4 = (const float4*)g_T;

    u64 tld[RANK][2];
    #pragma unroll
    for (int r = 0; r < RANK; r++) {
        float4 v = __ldg(&T4[r * B4 + b4]);
        tld[r][0] = pack2(v.x, v.y);
        tld[r][1] = pack2(v.z, v.w);
    }

    float4* out4 = (float4*)out;
    #pragma unroll 4
    for (int li = 0; li < L_TILE; li++) {
        u64 a0 = 0ull, a1 = 0ull;
        #pragma unroll
        for (int r = 0; r < RANK; r++) {
            u64 u2 = Us[r][li];
            fma2(a0, u2, tld[r][0]);
            fma2(a1, u2, tld[r][1]);
        }
        float2 lo = unpk2(a0);
        float2 hi = unpk2(a1);
        __stcs(&out4[(size_t)(l0 + li) * B4 + b4],
               make_float4(lo.x, lo.y, hi.x, hi.y));
    }
}

extern "C" void kernel_launch(void* const* d_in, const int* in_sizes, int n_in,
                              void* d_out, int out_size) {
    const float* inp = (const float*)d_in[0];  // [L, B]
    const float* U   = (const float*)d_in[1];  // [RANK, L]
    const float* V   = (const float*)d_in[2];  // [RANK, L]
    float* out = (float*)d_out;                // [L, B]

    dim3 g1(B4 / 256, M_SPLITS);
    vx_part_kernel<<<g1, 256>>>(inp, V);

    reduce_kernel<<<(RANK * B4) / 256, 256>>>();

    dim3 g3(B4 / 256, L_DIM / L_TILE);
    out_kernel<<<g3, 256>>>(U, out);
}

// round 6
// speedup vs baseline: 2.1934x; 1.1610x over previous
#include <cuda_runtime.h>

#define L_DIM 8192
#define B_DIM 4096
#define RANK 8
#define M_SPLITS 128
#define M_CHUNK (L_DIM / M_SPLITS)   // 64
#define B4 (B_DIM / 4)               // 1024 float4 lanes
#define L_TILE 32

typedef unsigned long long u64;

__device__ __forceinline__ void fma2(u64& d, u64 a, u64 b) {
    asm("fma.rn.f32x2 %0, %1, %2, %0;" : "+l"(d) : "l"(a), "l"(b));
}
__device__ __forceinline__ u64 dup2(float v) {
    u64 r;
    asm("mov.b64 %0, {%1, %1};" : "=l"(r) : "f"(v));
    return r;
}
__device__ __forceinline__ u64 pack2(float x, float y) {
    u64 r;
    asm("mov.b64 %0, {%1, %2};" : "=l"(r) : "f"(x), "f"(y));
    return r;
}
__device__ __forceinline__ float2 unpk2(u64 a) {
    float2 f;
    asm("mov.b64 {%0, %1}, %2;" : "=f"(f.x), "=f"(f.y) : "l"(a));
    return f;
}

// per-split partials: [M_SPLITS][RANK][B_DIM] = 16 MB (L2-resident)
__device__ float g_part[M_SPLITS * RANK * B_DIM];
// reduced T = V @ inputs -> [RANK, B]
__device__ float g_T[RANK * B_DIM];

// stage 1: part[s, r, b] = sum_{m in chunk s} V[r, m] * inputs[m, b]
// grid: (B4/256 = 4, M_SPLITS = 128), block: 256
// 2 CTAs/SM (~128 reg budget): room for 32 acc regs + 8 batched LDG.128 staging.
__global__ __launch_bounds__(256, 2) void vx_part_kernel(
    const float* __restrict__ inp, const float* __restrict__ V) {
    __shared__ u64 Vs[RANK][M_CHUNK];   // duplicated pairs, 4 KB

    const int s = blockIdx.y;
    const int m0 = s * M_CHUNK;
    for (int i = threadIdx.x; i < RANK * M_CHUNK; i += blockDim.x) {
        int r = i >> 6;               // / M_CHUNK
        int mi = i & (M_CHUNK - 1);
        Vs[r][mi] = dup2(V[r * L_DIM + m0 + mi]);
    }
    __syncthreads();

    const int b4 = blockIdx.x * blockDim.x + threadIdx.x;  // 0..1023
    const double2* in2 = (const double2*)inp;   // float4 as 2x u64 halves

    u64 acc[RANK][2];
    #pragma unroll
    for (int r = 0; r < RANK; r++) { acc[r][0] = 0ull; acc[r][1] = 0ull; }

    #pragma unroll 8
    for (int mi = 0; mi < M_CHUNK; mi++) {
        double2 x = __ldcs(&in2[(size_t)(m0 + mi) * B4 + b4]);
        u64 xlo = (u64)__double_as_longlong(x.x);
        u64 xhi = (u64)__double_as_longlong(x.y);
        #pragma unroll
        for (int r = 0; r < RANK; r++) {
            u64 v2 = Vs[r][mi];
            fma2(acc[r][0], v2, xlo);
            fma2(acc[r][1], v2, xhi);
        }
    }

    float4* p4 = (float4*)g_part;
    #pragma unroll
    for (int r = 0; r < RANK; r++) {
        float2 lo = unpk2(acc[r][0]);
        float2 hi = unpk2(acc[r][1]);
        p4[((size_t)s * RANK + r) * B4 + b4] = make_float4(lo.x, lo.y, hi.x, hi.y);
    }
}

// stage 2: T[r, b] = sum_s part[s, r, b]   (reads from L2)
// grid: RANK*B4/256 = 32 blocks, block: 256 (one float4 per thread)
__global__ __launch_bounds__(256) void reduce_kernel() {
    const int idx = blockIdx.x * blockDim.x + threadIdx.x;  // 0..8191
    const float4* p4 = (const float4*)g_part;

    float4 acc = make_float4(0.f, 0.f, 0.f, 0.f);
    #pragma unroll 16
    for (int s = 0; s < M_SPLITS; s++) {
        float4 x = p4[(size_t)s * RANK * B4 + idx];
        acc.x += x.x; acc.y += x.y; acc.z += x.z; acc.w += x.w;
    }
    ((float4*)g_T)[idx] = acc;
}

// stage 3: out[l, b] = sum_r U[r, l] * T[r, b]
// grid: (B4/256 = 4, L_DIM / L_TILE = 256), block: 256
__global__ __launch_bounds__(256, 4) void out_kernel(
    const float* __restrict__ U, float* __restrict__ out) {
    __shared__ u64 Us[RANK][L_TILE];    // duplicated pairs, 2 KB

    const int l0 = blockIdx.y * L_TILE;
    for (int i = threadIdx.x; i < RANK * L_TILE; i += blockDim.x) {
        int r = i >> 5;               // / L_TILE
        int li = i & (L_TILE - 1);
        Us[r][li] = dup2(U[r * L_DIM + l0 + li]);
    }
    __syncthreads();

    const int b4 = blockIdx.x * blockDim.x + threadIdx.x;  // 0..1023
    const float4* T4 = (const float4*)g_T;

    u64 tld[RANK][2];
    #pragma unroll
    for (int r = 0; r < RANK; r++) {
        float4 v = __ldg(&T4[r * B4 + b4]);
        tld[r][0] = pack2(v.x, v.y);
        tld[r][1] = pack2(v.z, v.w);
    }

    float4* out4 = (float4*)out;
    #pragma unroll 4
    for (int li = 0; li < L_TILE; li++) {
        u64 a0 = 0ull, a1 = 0ull;
        #pragma unroll
        for (int r = 0; r < RANK; r++) {
            u64 u2 = Us[r][li];
            fma2(a0, u2, tld[r][0]);
            fma2(a1, u2, tld[r][1]);
        }
        float2 lo = unpk2(a0);
        float2 hi = unpk2(a1);
        __stcs(&out4[(size_t)(l0 + li) * B4 + b4],
               make_float4(lo.x, lo.y, hi.x, hi.y));
    }
}

extern "C" void kernel_launch(void* const* d_in, const int* in_sizes, int n_in,
                              void* d_out, int out_size) {
    const float* inp = (const float*)d_in[0];  // [L, B]
    const float* U   = (const float*)d_in[1];  // [RANK, L]
    const float* V   = (const float*)d_in[2];  // [RANK, L]
    float* out = (float*)d_out;                // [L, B]

    dim3 g1(B4 / 256, M_SPLITS);
    vx_part_kernel<<<g1, 256>>>(inp, V);

    reduce_kernel<<<(RANK * B4) / 256, 256>>>();

    dim3 g3(B4 / 256, L_DIM / L_TILE);
    out_kernel<<<g3, 256>>>(U, out);
}

// round 7
// speedup vs baseline: 2.4120x; 1.0996x over previous
#include <cuda_runtime.h>

#define L_DIM 8192
#define B_DIM 4096
#define RANK 8
#define M_SPLITS 64
#define M_CHUNK (L_DIM / M_SPLITS)   // 128
#define B4 (B_DIM / 4)               // 1024 float4 lanes
#define L_TILE 64

typedef unsigned long long u64;

__device__ __forceinline__ void fma2(u64& d, u64 a, u64 b) {
    asm("fma.rn.f32x2 %0, %1, %2, %0;" : "+l"(d) : "l"(a), "l"(b));
}
__device__ __forceinline__ u64 dup2(float v) {
    u64 r;
    asm("mov.b64 %0, {%1, %1};" : "=l"(r) : "f"(v));
    return r;
}
__device__ __forceinline__ u64 pack2(float x, float y) {
    u64 r;
    asm("mov.b64 %0, {%1, %2};" : "=l"(r) : "f"(x), "f"(y));
    return r;
}
__device__ __forceinline__ float2 unpk2(u64 a) {
    float2 f;
    asm("mov.b64 {%0, %1}, %2;" : "=f"(f.x), "=f"(f.y) : "l"(a));
    return f;
}

// T = V @ inputs -> [RANK, B]. Zero-initialized at load; re-zeroed by out_kernel
// tail each launch, so every kernel_launch call starts from T == 0.
__device__ float g_T[RANK * B_DIM];
// per-b-quadrant completion counters for out_kernel (zero-init, self-resetting)
__device__ int g_count[4];

// stage 1: g_T[r, b] += sum_{m in chunk s} V[r, m] * inputs[m, b]  (RED.F32)
// grid: (B4/256 = 4, M_SPLITS = 64), block: 256, 2 CTAs/SM
__global__ __launch_bounds__(256, 2) void vx_kernel(
    const float* __restrict__ inp, const float* __restrict__ V) {
    __shared__ u64 Vs[RANK][M_CHUNK];   // duplicated pairs, 8 KB

    const int s = blockIdx.y;
    const int m0 = s * M_CHUNK;
    for (int i = threadIdx.x; i < RANK * M_CHUNK; i += blockDim.x) {
        int r = i >> 7;               // / M_CHUNK
        int mi = i & (M_CHUNK - 1);
        Vs[r][mi] = dup2(V[r * L_DIM + m0 + mi]);
    }
    __syncthreads();

    const int b4 = blockIdx.x * blockDim.x + threadIdx.x;  // 0..1023
    const double2* in2 = (const double2*)inp;   // float4 as 2x u64 halves

    u64 acc[RANK][2];
    #pragma unroll
    for (int r = 0; r < RANK; r++) { acc[r][0] = 0ull; acc[r][1] = 0ull; }

    #pragma unroll 8
    for (int mi = 0; mi < M_CHUNK; mi++) {
        double2 x = __ldcs(&in2[(size_t)(m0 + mi) * B4 + b4]);
        u64 xlo = (u64)__double_as_longlong(x.x);
        u64 xhi = (u64)__double_as_longlong(x.y);
        #pragma unroll
        for (int r = 0; r < RANK; r++) {
            u64 v2 = Vs[r][mi];
            fma2(acc[r][0], v2, xlo);
            fma2(acc[r][1], v2, xhi);
        }
    }

    const int b = b4 * 4;
    #pragma unroll
    for (int r = 0; r < RANK; r++) {
        float2 lo = unpk2(acc[r][0]);
        float2 hi = unpk2(acc[r][1]);
        float* dst = &g_T[r * B_DIM + b];
        atomicAdd(dst + 0, lo.x);
        atomicAdd(dst + 1, lo.y);
        atomicAdd(dst + 2, hi.x);
        atomicAdd(dst + 3, hi.y);
    }
}

// stage 2: out[l, b] = sum_r U[r, l] * T[r, b]; tail re-zeroes T for next launch
// grid: (B4/256 = 4, L_DIM / L_TILE = 128), block: 256
__global__ __launch_bounds__(256, 4) void out_kernel(
    const float* __restrict__ U, float* __restrict__ out) {
    __shared__ __align__(16) u64 Us[L_TILE][RANK];  // transposed, dup pairs, 4 KB
    __shared__ int s_last;

    const int t = threadIdx.x;
    const int l0 = blockIdx.y * L_TILE;
    for (int i = t; i < RANK * L_TILE; i += blockDim.x) {
        int li = i >> 3;
        int r = i & 7;
        Us[li][r] = dup2(U[r * L_DIM + l0 + li]);
    }
    __syncthreads();

    const int b4 = blockIdx.x * blockDim.x + t;  // 0..1023
    const float4* T4 = (const float4*)g_T;

    u64 tld[RANK][2];
    #pragma unroll
    for (int r = 0; r < RANK; r++) {
        float4 v = __ldg(&T4[r * B4 + b4]);
        tld[r][0] = pack2(v.x, v.y);
        tld[r][1] = pack2(v.z, v.w);
    }

    float4* out4 = (float4*)out;
    #pragma unroll 4
    for (int li = 0; li < L_TILE; li++) {
        // 4x LDS.128 (broadcast) for the 8 rank operands of this li
        const ulonglong2* up = (const ulonglong2*)&Us[li][0];
        ulonglong2 u01 = up[0], u23 = up[1], u45 = up[2], u67 = up[3];
        u64 a0 = 0ull, a1 = 0ull;
        fma2(a0, u01.x, tld[0][0]); fma2(a1, u01.x, tld[0][1]);
        fma2(a0, u01.y, tld[1][0]); fma2(a1, u01.y, tld[1][1]);
        fma2(a0, u23.x, tld[2][0]); fma2(a1, u23.x, tld[2][1]);
        fma2(a0, u23.y, tld[3][0]); fma2(a1, u23.y, tld[3][1]);
        fma2(a0, u45.x, tld[4][0]); fma2(a1, u45.x, tld[4][1]);
        fma2(a0, u45.y, tld[5][0]); fma2(a1, u45.y, tld[5][1]);
        fma2(a0, u67.x, tld[6][0]); fma2(a1, u67.x, tld[6][1]);
        fma2(a0, u67.y, tld[7][0]); fma2(a1, u67.y, tld[7][1]);
        float2 lo = unpk2(a0);
        float2 hi = unpk2(a1);
        __stcs(&out4[(size_t)(l0 + li) * B4 + b4],
               make_float4(lo.x, lo.y, hi.x, hi.y));
    }

    // --- tail: last CTA of this b-quadrant re-zeroes its T slice + counter ---
    __syncthreads();
    __threadfence();
    if (t == 0) {
        int old = atomicAdd(&g_count[blockIdx.x], 1);
        s_last = (old == (int)gridDim.y - 1);
    }
    __syncthreads();
    if (s_last) {
        float4 z = make_float4(0.f, 0.f, 0.f, 0.f);
        float4* Tz = (float4*)g_T;
        #pragma unroll
        for (int r = 0; r < RANK; r++)
            Tz[r * B4 + b4] = z;
        __threadfence();
        if (t == 0) atomicExch(&g_count[blockIdx.x], 0);
    }
}

extern "C" void kernel_launch(void* const* d_in, const int* in_sizes, int n_in,
                              void* d_out, int out_size) {
    const float* inp = (const float*)d_in[0];  // [L, B]
    const float* U   = (const float*)d_in[1];  // [RANK, L]
    const float* V   = (const float*)d_in[2];  // [RANK, L]
    float* out = (float*)d_out;                // [L, B]

    dim3 g1(B4 / 256, M_SPLITS);
    vx_kernel<<<g1, 256>>>(inp, V);

    dim3 g2(B4 / 256, L_DIM / L_TILE);
    out_kernel<<<g2, 256>>>(U, out);
}